// round 16
// baseline (speedup 1.0000x reference)
#include <cuda_runtime.h>
#include <cstdint>
#define DI __device__ __forceinline__

__device__ float g_p [8192*128];
__device__ float g_v [8192*128];
__device__ float g_P1[8192*128];
__device__ float g_V1[8192*128];
__device__ float g_Wfp[128*128];
__device__ float g_Wfv[128*128];
__device__ float g_biasF[2*128];
// fp16 fragment packs (k64 slabs, stride 36)
__device__ __align__(16) unsigned g_W1h [4*4608];   // W1c|W1d rows 256..511
__device__ __align__(16) unsigned g_W2h [2*4608];
__device__ __align__(16) unsigned g_Wph [2*4608];
__device__ __align__(16) unsigned g_Wfph[2*4608];
__device__ __align__(16) unsigned g_Wvh [2*4608];
__device__ __align__(16) unsigned g_Wfvh[2*4608];

DI unsigned pk2(float lo, float hi){
    unsigned r;
    asm("cvt.rn.f16x2.f32 %0, %1, %2;" : "=r"(r) : "f"(hi), "f"(lo));
    return r;
}
DI float frcp(float x){ float r; asm("rcp.approx.f32 %0, %1;":"=f"(r):"f"(x)); return r; }
DI void mma16(float* c, unsigned a0,unsigned a1,unsigned a2,unsigned a3,unsigned b0,unsigned b1){
    asm volatile("mma.sync.aligned.m16n8k16.row.col.f32.f16.f16.f32 "
        "{%0,%1,%2,%3},{%4,%5,%6,%7},{%8,%9},{%0,%1,%2,%3};\n"
        :"+f"(c[0]),"+f"(c[1]),"+f"(c[2]),"+f"(c[3])
        :"r"(a0),"r"(a1),"r"(a2),"r"(a3),"r"(b0),"r"(b1)); }
DI uint32_t s2u(const void* p){ uint32_t a; asm("{ .reg .u64 t; cvta.to.shared.u64 t, %1; cvt.u32.u64 %0, t; }":"=r"(a):"l"(p)); return a; }

// ---- bulk async copy (UBLKCP) + mbarrier ----
DI void bulkcp(uint32_t dst, const void* src, uint32_t bytes, uint32_t mbar){
    asm volatile("cp.async.bulk.shared::cta.global.mbarrier::complete_tx::bytes [%0], [%1], %2, [%3];"
                 :: "r"(dst), "l"(src), "r"(bytes), "r"(mbar) : "memory");
}
#define MBAR_INIT(a,n)   asm volatile("mbarrier.init.shared.b64 [%0], %1;"::"r"(a),"r"(n):"memory")
#define MBAR_EXPECT(a,b) asm volatile("mbarrier.arrive.expect_tx.shared.b64 _, [%0], %1;"::"r"(a),"r"(b):"memory")
DI void mbwait(uint32_t mb, uint32_t par){
    uint32_t done;
    asm volatile("{\n\t.reg .pred p;\n\tmbarrier.try_wait.parity.acquire.cta.shared::cta.b64 p, [%1], %2;\n\tselp.b32 %0,1,0,p;\n\t}"
        :"=r"(done):"r"(mb),"r"(par):"memory");
    if(!done) asm volatile("{\n\t.reg .pred P1;\n\tWL_%=:\n\t"
        "mbarrier.try_wait.parity.acquire.cta.shared::cta.b64 P1, [%0], %1, 0x989680;\n\t"
        "@P1 bra.uni WD_%=;\n\tbra.uni WL_%=;\n\tWD_%=:\n\t}"::"r"(mb),"r"(par):"memory");
}

__global__ __launch_bounds__(256) void prep_kernel(
    const float* __restrict__ Wp, const float* __restrict__ bp,
    const float* __restrict__ Wv, const float* __restrict__ bv,
    const float* __restrict__ W1){
    __shared__ float Wc_s[32*128];
    __shared__ float Wr_s[16*128];
    int cb = blockIdx.x, isv = cb>=8, rb = (cb&7)*16;
    const float* Wx  = isv? Wv: Wp;
    const float* W1x = W1 + (isv? 128*128: 0);
    float* outW = isv? g_Wfv: g_Wfp;
    int t = threadIdx.x;
    for(int i=t; i<16*128; i+=256) Wr_s[i] = Wx[(rb+(i>>7))*128 + (i&127)];
    float acc[8];
#pragma unroll
    for(int ii=0; ii<8; ii++) acc[ii]=0.f;
    int j = t&127, ih = (t>>7)*8;
    for(int kc=0; kc<4; kc++){
        __syncthreads();
        for(int i=t; i<32*128; i+=256) Wc_s[i] = W1x[(kc*32+(i>>7))*128 + (i&127)];
        __syncthreads();
        for(int k=0; k<32; k++){
            float b = Wc_s[k*128+j];
#pragma unroll
            for(int ii=0; ii<8; ii++) acc[ii] += Wr_s[(ih+ii)*128 + kc*32+k]*b;
        }
    }
#pragma unroll
    for(int ii=0; ii<8; ii++) outW[(rb+ih+ii)*128 + j] = acc[ii];
    if((cb&7)==0 && t<128){
        const float* bx = isv? bv: bp;
        float s=0.f;
        for(int k=0;k<128;k++) s += bx[k]*W1x[k*128+t];
        g_biasF[isv*128+t] = s;
    }
}

// fp16 fragment pack, 14 k64 slabs. grid 14 x 128.
__global__ __launch_bounds__(128) void pack16_kernel(
    const float* __restrict__ W1, const float* __restrict__ W2,
    const float* __restrict__ Wp, const float* __restrict__ Wv){
    int sid = blockIdx.x;
    const float* src; unsigned* dst;
    if      (sid<4) { src = W1 + (256 + sid*64)*128; dst = g_W1h  + sid*4608; }
    else if (sid<6) { src = W2 + (sid-4)*64*128;     dst = g_W2h  + (sid-4)*4608; }
    else if (sid<8) { src = Wp + (sid-6)*64*128;     dst = g_Wph  + (sid-6)*4608; }
    else if (sid<10){ src = g_Wfp + (sid-8)*64*128;  dst = g_Wfph + (sid-8)*4608; }
    else if (sid<12){ src = Wv + (sid-10)*64*128;    dst = g_Wvh  + (sid-10)*4608; }
    else            { src = g_Wfv + (sid-12)*64*128; dst = g_Wfvh + (sid-12)*4608; }
    int t=threadIdx.x, lane=t&31, ks=t>>5, gid=lane>>2, t4=lane&3;
#pragma unroll
    for(int j=0;j<16;j++)
#pragma unroll
        for(int r=0;r<2;r++){
            int k0 = ks*16 + 2*t4 + 8*r;
            dst[(ks*32+lane)*36 + 2*j + r] =
                pk2(src[k0*128 + 8*j + gid], src[(k0+1)*128 + 8*j + gid]);
        }
}

DI void mmaW(float (*acc)[4], const unsigned ah[4][4], const unsigned* Wb, int lane){
#pragma unroll
    for(int ks=0;ks<4;ks++){
        const uint4* bb = (const uint4*)(Wb + (ks*32+lane)*36);
#pragma unroll
        for(int jj=0;jj<8;jj++){
            uint4 b = bb[jj];
            mma16(acc[2*jj],  ah[ks][0],ah[ks][1],ah[ks][2],ah[ks][3],b.x,b.y);
            mma16(acc[2*jj+1],ah[ks][0],ah[ks][1],ah[ks][2],ah[ks][3],b.z,b.w);
        }
    }
}

// ---------------------------------------------------------------------------
// pv (fp16): 256 CTAs x 256 thr (R15, passing). 109576 B smem.
// ---------------------------------------------------------------------------
__global__ __launch_bounds__(256,2) void pv_kernel(
    const float* __restrict__ price, const float* __restrict__ liquid,
    const float* __restrict__ bp, const float* __restrict__ bv){
    extern __shared__ float smpv[];
    unsigned* Wres = (unsigned*)smpv;
    float* in_s   = smpv + 18432;
    float* bias_s = smpv + 27136;
    int cb=blockIdx.x, isv=cb>=128, rb=(cb&127)*64;
    const float* in_g = (isv? liquid: price) + (size_t)rb*128;
    const unsigned* packA = isv? g_Wvh : g_Wph;
    const unsigned* packB = isv? g_Wfvh: g_Wfph;
    float* outA = (isv? g_v : g_p)  + (size_t)rb*128;
    float* outB = (isv? g_V1: g_P1) + (size_t)rb*128;
    int t=threadIdx.x, w=t>>5, lane=t&31, gid=lane>>2, t4=lane&3;
    int rowgrp=w&3, pk=w>>2, mbase=rowgrp*16;
    uint32_t sb = s2u(smpv);
    uint32_t mb = sb + 27392*4;

    if(t==0) MBAR_INIT(mb, 1);
    __syncthreads();
    if(t==0){
        MBAR_EXPECT(mb, 4*18432 + 64*512 + 1024);
        bulkcp(sb,          packA,        18432, mb);
        bulkcp(sb+18432,    packA+4608,   18432, mb);
        bulkcp(sb+2*18432,  packB,        18432, mb);
        bulkcp(sb+3*18432,  packB+4608,   18432, mb);
        uint32_t ina = sb + 18432*4;
        for(int r=0;r<64;r++) bulkcp(ina + r*544, in_g + r*128, 512, mb);
        bulkcp(sb + 27136*4,       isv? bv: bp,          512, mb);
        bulkcp(sb + 27136*4 + 512, g_biasF + isv*128,    512, mb);
    }

    float acc[16][4];
#pragma unroll
    for(int j=0;j<16;j++)
#pragma unroll
        for(int e=0;e<4;e++) acc[j][e]=0.f;

    mbwait(mb, 0);
    const float* r0 = in_s + (mbase+gid)*136 + 2*t4;
    const float* r1 = r0 + 8*136;

#pragma unroll
    for(int s=0;s<2;s++){
        unsigned ah[4][4];
        const int kb0 = s*64;
#pragma unroll
        for(int ks=0;ks<4;ks++){
            int ko = kb0 + ks*16;
            float2 a0=*(const float2*)&r0[ko],   c0=*(const float2*)&r1[ko];
            float2 a1=*(const float2*)&r0[ko+8], c1=*(const float2*)&r1[ko+8];
            ah[ks][0]=pk2(a0.x,a0.y);
            ah[ks][1]=pk2(c0.x,c0.y);
            ah[ks][2]=pk2(a1.x,a1.y);
            ah[ks][3]=pk2(c1.x,c1.y);
        }
        mmaW(acc, ah, Wres + pk*9216 + s*4608, lane);
    }

    float* outX = pk? outB: outA;
    float* o0 = outX + (size_t)(mbase+gid)*128;
    float* o1 = o0 + 8*128;
#pragma unroll
    for(int j=0;j<16;j++){
        int c=j*8+2*t4;
        float b0=bias_s[pk*128+c], b1=bias_s[pk*128+c+1];
        *(float2*)&o0[c] = make_float2(acc[j][0]+b0, acc[j][1]+b1);
        *(float2*)&o1[c] = make_float2(acc[j][2]+b0, acc[j][3]+b1);
    }
}

// A-fragment build, TWO row-blocks (mi), bases include +2*t4.
// s: 0/1 prod k0-63/k64-127, 2/3 absdiff.
DI void buildA2(unsigned ah[4][2][4], const float* pw, const float* v0, int s){
    const int kb0 = (s&1)*64;
    const float* pwk = pw + kb0;
    const float* vk  = v0 + kb0;
#pragma unroll
    for(int ks=0;ks<4;ks++){
        int ko = ks*16;
        float2 pl = *(const float2*)&pwk[ko];
        float2 ph = *(const float2*)&pwk[ko+8];
#pragma unroll
        for(int mi=0;mi<2;mi++){
            const float* vb = vk + mi*16*136;
            float2 a0=*(const float2*)&vb[ko];
            float2 c0=*(const float2*)&vb[8*136+ko];
            float2 a1=*(const float2*)&vb[ko+8];
            float2 c1=*(const float2*)&vb[8*136+ko+8];
            if(s<2){
                ah[ks][mi][0]=pk2(pl.x*a0.x, pl.y*a0.y);
                ah[ks][mi][1]=pk2(pl.x*c0.x, pl.y*c0.y);
                ah[ks][mi][2]=pk2(ph.x*a1.x, ph.y*a1.y);
                ah[ks][mi][3]=pk2(ph.x*c1.x, ph.y*c1.y);
            }else{
                ah[ks][mi][0]=pk2(fabsf(pl.x-a0.x), fabsf(pl.y-a0.y));
                ah[ks][mi][1]=pk2(fabsf(pl.x-c0.x), fabsf(pl.y-c0.y));
                ah[ks][mi][2]=pk2(fabsf(ph.x-a1.x), fabsf(ph.y-a1.y));
                ah[ks][mi][3]=pk2(fabsf(ph.x-c1.x), fabsf(ph.y-c1.y));
            }
        }
    }
}

// MMA over one slab, 2 row-blocks x 4 col-uint4 (ch half of N).
DI void mmaW2(float (*acc)[8][4], const unsigned ah[4][2][4],
              const unsigned* Wb, int lane, int ch){
#pragma unroll
    for(int ks=0;ks<4;ks++){
        const uint4* bb = (const uint4*)(Wb + (ks*32+lane)*36) + ch*4;
#pragma unroll
        for(int jj=0;jj<4;jj++){
            uint4 b = bb[jj];
            mma16(acc[0][2*jj],  ah[ks][0][0],ah[ks][0][1],ah[ks][0][2],ah[ks][0][3],b.x,b.y);
            mma16(acc[0][2*jj+1],ah[ks][0][0],ah[ks][0][1],ah[ks][0][2],ah[ks][0][3],b.z,b.w);
            mma16(acc[1][2*jj],  ah[ks][1][0],ah[ks][1][1],ah[ks][1][2],ah[ks][1][3],b.x,b.y);
            mma16(acc[1][2*jj+1],ah[ks][1][0],ah[ks][1][1],ah[ks][1][2],ah[ks][1][3],b.z,b.w);
        }
    }
}

// GEMM2 slab: A from staged h (smem), 2 row-blocks x ch col-half.
DI void g2slab(float (*acc)[8][4], const unsigned* hu, const unsigned* Wb,
               int lane, int ch, int rg, int gid, int t4, int s2){
#pragma unroll
    for(int ks=0;ks<4;ks++){
        int ksg = s2*4+ks;
        unsigned a[2][4];
#pragma unroll
        for(int mi=0;mi<2;mi++){
            const unsigned* hr = hu + (rg*32+mi*16+gid)*68 + ksg*8 + t4;
            a[mi][0]=hr[0];
            a[mi][1]=hr[8*68];
            a[mi][2]=hr[4];
            a[mi][3]=hr[8*68+4];
        }
        const uint4* bb = (const uint4*)(Wb + (ks*32+lane)*36) + ch*4;
#pragma unroll
        for(int jj=0;jj<4;jj++){
            uint4 b = bb[jj];
            mma16(acc[0][2*jj],  a[0][0],a[0][1],a[0][2],a[0][3],b.x,b.y);
            mma16(acc[0][2*jj+1],a[0][0],a[0][1],a[0][2],a[0][3],b.z,b.w);
            mma16(acc[1][2*jj],  a[1][0],a[1][1],a[1][2],a[1][3],b.x,b.y);
            mma16(acc[1][2*jj+1],a[1][0],a[1][1],a[1][2],a[1][3],b.z,b.w);
        }
    }
}

// ---------------------------------------------------------------------------
// pair_main v5 (rg x ch): 2048 x 256 thr / 8 warps.
// warp w: rg=w>>1 -> n=rg, rows rg*32 + mi*16+gid(+8); ch=w&1 -> cols ch*64..+63.
// acc[2][8][4]=64 regs. B reads per slab HALVED (4 uint4/ks). h staged fp16 in
// smem (stride-68 u32, aliases v/V1 after GEMM1). Bulk loads + 4-slot W ring.
// smem u32: Wbuf 4x4608 | b1@18432 b2@18560 | v@18688(32x136) | V1@23040 |
//   p@27392(4x136) | P1@27936..28480 | mbars@28480. h_u aliases @18688 (8704).
// total 113960 B -> 2 CTAs/SM.
// ---------------------------------------------------------------------------
__global__ __launch_bounds__(256,2) void pair_main_kernel(
    const float* __restrict__ b1v, const float* __restrict__ b2v,
    float* __restrict__ out){
    extern __shared__ float sm[];
    unsigned* Wbuf = (unsigned*)sm;
    float* b1_s = sm + 18432;
    float* b2_s = sm + 18560;
    float* v_s  = sm + 18688;
    float* V1_s = sm + 23040;
    float* p_s  = sm + 27392;
    float* P1_s = sm + 27936;
    unsigned* h_u = (unsigned*)(sm + 18688);   // aliases v_s+V1_s after GEMM1
    const int bt=blockIdx.x>>3, pb=blockIdx.x&7;
    const int t=threadIdx.x, w=t>>5, lane=t&31;
    const int gid=lane>>2, t4=lane&3;
    const int rg=w>>1, ch=w&1;
    uint32_t Wba = s2u(Wbuf);
    uint32_t m0 = Wba + 28480*4;
    uint32_t m1 = m0+8, m2 = m0+16, m3 = m0+24, mt = m0+32;

    if(t==0){
        MBAR_INIT(m0,1); MBAR_INIT(m1,1); MBAR_INIT(m2,1);
        MBAR_INIT(m3,1); MBAR_INIT(mt,1);
    }
    __syncthreads();
    if(t==0){
        MBAR_EXPECT(m0,18432); bulkcp(Wba,         g_W1h,        18432, m0);
        MBAR_EXPECT(m1,18432); bulkcp(Wba+18432,   g_W1h+4608,   18432, m1);
        MBAR_EXPECT(m2,18432); bulkcp(Wba+2*18432, g_W1h+2*4608, 18432, m2);
        MBAR_EXPECT(m3,18432); bulkcp(Wba+3*18432, g_W1h+3*4608, 18432, m3);
        MBAR_EXPECT(mt, 32*512*2 + 4*512*2 + 1024);
        uint32_t vA = s2u(v_s), vB = s2u(V1_s), pA = s2u(p_s), pB = s2u(P1_s);
        const float* vg  = g_v  + (size_t)bt*4096;
        const float* V1g = g_V1 + (size_t)bt*4096;
        for(int m=0;m<32;m++){
            bulkcp(vA + m*544, vg  + m*128, 512, mt);
            bulkcp(vB + m*544, V1g + m*128, 512, mt);
        }
        const float* pg  = g_p  + (size_t)(bt*32+pb*4)*128;
        const float* P1g = g_P1 + (size_t)(bt*32+pb*4)*128;
        for(int nn=0;nn<4;nn++){
            bulkcp(pA + nn*544, pg  + nn*128, 512, mt);
            bulkcp(pB + nn*544, P1g + nn*128, 512, mt);
        }
        bulkcp(s2u(b1_s), b1v, 512, mt);
        bulkcp(s2u(b2_s), b2v, 512, mt);
    }

    float acc[2][8][4];
#pragma unroll
    for(int mi=0;mi<2;mi++)
#pragma unroll
        for(int j=0;j<8;j++)
#pragma unroll
            for(int e=0;e<4;e++) acc[mi][j][e]=0.f;

    mbwait(mt, 0);
    const float* pw = p_s + rg*136 + 2*t4;
    const float* v0 = v_s + gid*136 + 2*t4;

    unsigned ah[4][2][4];
    buildA2(ah, pw, v0, 0);
    mbwait(m0, 0);
    mmaW2(acc, ah, Wbuf, lane, ch);
    buildA2(ah, pw, v0, 1);
    mbwait(m1, 0);
    mmaW2(acc, ah, Wbuf+4608, lane, ch);
    __syncthreads();
    if(t==0){
        MBAR_EXPECT(m0,18432); bulkcp(Wba,       g_W2h,      18432, m0);
        MBAR_EXPECT(m1,18432); bulkcp(Wba+18432, g_W2h+4608, 18432, m1);
    }
    buildA2(ah, pw, v0, 2);
    mbwait(m2, 0);
    mmaW2(acc, ah, Wbuf+2*4608, lane, ch);
    buildA2(ah, pw, v0, 3);
    mbwait(m3, 0);
    mmaW2(acc, ah, Wbuf+3*4608, lane, ch);

    // ------- epilogue 1: silu via batched rcp -> h2 regs --------------------
    unsigned h2[2][8][2];
#pragma unroll
    for(int mi=0;mi<2;mi++){
        const float* V0p = &V1_s[(mi*16+gid)*136];
        const float* V1p = V0p + 8*136;
        const float* P1p = &P1_s[rg*136];
#pragma unroll
        for(int jl=0;jl<8;jl++){
            int c0 = ch*64 + jl*8 + 2*t4;
            float2 P  = *(const float2*)&P1p[c0];
            float2 Bb = *(const float2*)&b1_s[c0];
            float2 Va = *(const float2*)&V0p[c0];
            float2 Vb = *(const float2*)&V1p[c0];
            float x0=acc[mi][jl][0]+P.x+Va.x+Bb.x;
            float x1=acc[mi][jl][1]+P.y+Va.y+Bb.y;
            float x2=acc[mi][jl][2]+P.x+Vb.x+Bb.x;
            float x3=acc[mi][jl][3]+P.y+Vb.y+Bb.y;
            float u0=1.f+__expf(-x0), u1=1.f+__expf(-x1);
            float u2=1.f+__expf(-x2), u3=1.f+__expf(-x3);
            float p01=u0*u1, p23=u2*u3;
            float r = frcp(p01*p23);
            float r01 = r*p23, r23 = r*p01;
            x0 = x0*(r01*u1); x1 = x1*(r01*u0);
            x2 = x2*(r23*u3); x3 = x3*(r23*u2);
            h2[mi][jl][0]=pk2(x0,x1);
            h2[mi][jl][1]=pk2(x2,x3);
            acc[mi][jl][0]=0.f; acc[mi][jl][1]=0.f;
            acc[mi][jl][2]=0.f; acc[mi][jl][3]=0.f;
        }
    }
    __syncthreads();   // all reads of v_s/V1_s done -> safe to alias with h_u

    // stage h (fp16 pairs): h_u[row*68 + kpair], kpair = ch*32 + jl*4 + t4
#pragma unroll
    for(int mi=0;mi<2;mi++){
        int r0 = rg*32 + mi*16 + gid;
#pragma unroll
        for(int jl=0;jl<8;jl++){
            int kp = ch*32 + jl*4 + t4;
            h_u[r0*68 + kp]       = h2[mi][jl][0];
            h_u[(r0+8)*68 + kp]   = h2[mi][jl][1];
        }
    }
    __syncthreads();   // publish h

    // ---- GEMM2: W2 slabs (slots 0,1 phase 1), A from staged h --------------
    mbwait(m0, 1);
    g2slab(acc, h_u, Wbuf, lane, ch, rg, gid, t4, 0);
    mbwait(m1, 1);
    g2slab(acc, h_u, Wbuf+4608, lane, ch, rg, gid, t4, 1);

    // ------------- epilogue 2: + b2, direct stores --------------------------
    const size_t ob = (size_t)blockIdx.x*16384;
#pragma unroll
    for(int mi=0;mi<2;mi++){
        float* o0 = out + ob + (size_t)(rg*32+mi*16+gid)*128 + ch*64;
        float* o1 = o0 + 8*128;
#pragma unroll
        for(int jl=0;jl<8;jl++){
            int c  = jl*8 + 2*t4;
            int cg = ch*64 + c;
            *(float2*)&o0[c] = make_float2(acc[mi][jl][0]+b2_s[cg], acc[mi][jl][1]+b2_s[cg+1]);
            *(float2*)&o1[c] = make_float2(acc[mi][jl][2]+b2_s[cg], acc[mi][jl][3]+b2_s[cg+1]);
        }
    }
}

extern "C" void kernel_launch(void* const* d_in, const int* in_sizes, int n_in,
                              void* d_out, int out_size){
    const float* price =(const float*)d_in[0];
    const float* liquid=(const float*)d_in[1];
    const float* W_p=(const float*)d_in[2];
    const float* b_p=(const float*)d_in[3];
    const float* W_v=(const float*)d_in[4];
    const float* b_v=(const float*)d_in[5];
    const float* W1 =(const float*)d_in[6];
    const float* b1 =(const float*)d_in[7];
    const float* W2 =(const float*)d_in[8];
    const float* b2 =(const float*)d_in[9];
    float* out=(float*)d_out;
    cudaFuncSetAttribute(pv_kernel, cudaFuncAttributeMaxDynamicSharedMemorySize, 110592);
    cudaFuncSetAttribute(pair_main_kernel, cudaFuncAttributeMaxDynamicSharedMemorySize, 114688);
    prep_kernel<<<16, 256>>>(W_p, b_p, W_v, b_v, W1);
    pack16_kernel<<<14, 128>>>(W1, W2, W_p, W_v);
    pv_kernel<<<256, 256, 109576>>>(price, liquid, b_p, b_v);
    pair_main_kernel<<<2048, 256, 113960>>>(b1, b2, out);
}

// round 17
// speedup vs baseline: 1.1305x; 1.1305x over previous
#include <cuda_runtime.h>
#include <cstdint>
#define DI __device__ __forceinline__

__device__ float g_p [8192*128];
__device__ float g_v [8192*128];
__device__ float g_P1[8192*128];
__device__ float g_V1[8192*128];
__device__ float g_Wfp[128*128];
__device__ float g_Wfv[128*128];
__device__ float g_biasF[2*128];
// fp16 fragment packs (k64 slabs, stride 36)
__device__ __align__(16) unsigned g_W1h [4*4608];   // W1c|W1d rows 256..511
__device__ __align__(16) unsigned g_W2h [2*4608];
__device__ __align__(16) unsigned g_Wph [2*4608];
__device__ __align__(16) unsigned g_Wfph[2*4608];
__device__ __align__(16) unsigned g_Wvh [2*4608];
__device__ __align__(16) unsigned g_Wfvh[2*4608];

DI unsigned pk2(float lo, float hi){
    unsigned r;
    asm("cvt.rn.f16x2.f32 %0, %1, %2;" : "=r"(r) : "f"(hi), "f"(lo));
    return r;
}
DI float frcp(float x){ float r; asm("rcp.approx.f32 %0, %1;":"=f"(r):"f"(x)); return r; }
DI void mma16(float* c, unsigned a0,unsigned a1,unsigned a2,unsigned a3,unsigned b0,unsigned b1){
    asm volatile("mma.sync.aligned.m16n8k16.row.col.f32.f16.f16.f32 "
        "{%0,%1,%2,%3},{%4,%5,%6,%7},{%8,%9},{%0,%1,%2,%3};\n"
        :"+f"(c[0]),"+f"(c[1]),"+f"(c[2]),"+f"(c[3])
        :"r"(a0),"r"(a1),"r"(a2),"r"(a3),"r"(b0),"r"(b1)); }
DI uint32_t s2u(const void* p){ uint32_t a; asm("{ .reg .u64 t; cvta.to.shared.u64 t, %1; cvt.u32.u64 %0, t; }":"=r"(a):"l"(p)); return a; }

// ---- bulk async copy (UBLKCP) + mbarrier ----
DI void bulkcp(uint32_t dst, const void* src, uint32_t bytes, uint32_t mbar){
    asm volatile("cp.async.bulk.shared::cta.global.mbarrier::complete_tx::bytes [%0], [%1], %2, [%3];"
                 :: "r"(dst), "l"(src), "r"(bytes), "r"(mbar) : "memory");
}
#define MBAR_INIT(a,n)   asm volatile("mbarrier.init.shared.b64 [%0], %1;"::"r"(a),"r"(n):"memory")
#define MBAR_EXPECT(a,b) asm volatile("mbarrier.arrive.expect_tx.shared.b64 _, [%0], %1;"::"r"(a),"r"(b):"memory")
DI void mbwait(uint32_t mb, uint32_t par){
    uint32_t done;
    asm volatile("{\n\t.reg .pred p;\n\tmbarrier.try_wait.parity.acquire.cta.shared::cta.b64 p, [%1], %2;\n\tselp.b32 %0,1,0,p;\n\t}"
        :"=r"(done):"r"(mb),"r"(par):"memory");
    if(!done) asm volatile("{\n\t.reg .pred P1;\n\tWL_%=:\n\t"
        "mbarrier.try_wait.parity.acquire.cta.shared::cta.b64 P1, [%0], %1, 0x989680;\n\t"
        "@P1 bra.uni WD_%=;\n\tbra.uni WL_%=;\n\tWD_%=:\n\t}"::"r"(mb),"r"(par):"memory");
}

__global__ __launch_bounds__(256) void prep_kernel(
    const float* __restrict__ Wp, const float* __restrict__ bp,
    const float* __restrict__ Wv, const float* __restrict__ bv,
    const float* __restrict__ W1){
    __shared__ float Wc_s[32*128];
    __shared__ float Wr_s[16*128];
    int cb = blockIdx.x, isv = cb>=8, rb = (cb&7)*16;
    const float* Wx  = isv? Wv: Wp;
    const float* W1x = W1 + (isv? 128*128: 0);
    float* outW = isv? g_Wfv: g_Wfp;
    int t = threadIdx.x;
    for(int i=t; i<16*128; i+=256) Wr_s[i] = Wx[(rb+(i>>7))*128 + (i&127)];
    float acc[8];
#pragma unroll
    for(int ii=0; ii<8; ii++) acc[ii]=0.f;
    int j = t&127, ih = (t>>7)*8;
    for(int kc=0; kc<4; kc++){
        __syncthreads();
        for(int i=t; i<32*128; i+=256) Wc_s[i] = W1x[(kc*32+(i>>7))*128 + (i&127)];
        __syncthreads();
        for(int k=0; k<32; k++){
            float b = Wc_s[k*128+j];
#pragma unroll
            for(int ii=0; ii<8; ii++) acc[ii] += Wr_s[(ih+ii)*128 + kc*32+k]*b;
        }
    }
#pragma unroll
    for(int ii=0; ii<8; ii++) outW[(rb+ih+ii)*128 + j] = acc[ii];
    if((cb&7)==0 && t<128){
        const float* bx = isv? bv: bp;
        float s=0.f;
        for(int k=0;k<128;k++) s += bx[k]*W1x[k*128+t];
        g_biasF[isv*128+t] = s;
    }
}

// fp16 fragment pack, 14 k64 slabs. grid 14 x 128.
__global__ __launch_bounds__(128) void pack16_kernel(
    const float* __restrict__ W1, const float* __restrict__ W2,
    const float* __restrict__ Wp, const float* __restrict__ Wv){
    int sid = blockIdx.x;
    const float* src; unsigned* dst;
    if      (sid<4) { src = W1 + (256 + sid*64)*128; dst = g_W1h  + sid*4608; }
    else if (sid<6) { src = W2 + (sid-4)*64*128;     dst = g_W2h  + (sid-4)*4608; }
    else if (sid<8) { src = Wp + (sid-6)*64*128;     dst = g_Wph  + (sid-6)*4608; }
    else if (sid<10){ src = g_Wfp + (sid-8)*64*128;  dst = g_Wfph + (sid-8)*4608; }
    else if (sid<12){ src = Wv + (sid-10)*64*128;    dst = g_Wvh  + (sid-10)*4608; }
    else            { src = g_Wfv + (sid-12)*64*128; dst = g_Wfvh + (sid-12)*4608; }
    int t=threadIdx.x, lane=t&31, ks=t>>5, gid=lane>>2, t4=lane&3;
#pragma unroll
    for(int j=0;j<16;j++)
#pragma unroll
        for(int r=0;r<2;r++){
            int k0 = ks*16 + 2*t4 + 8*r;
            dst[(ks*32+lane)*36 + 2*j + r] =
                pk2(src[k0*128 + 8*j + gid], src[(k0+1)*128 + 8*j + gid]);
        }
}

DI void mmaW(float (*acc)[4], const unsigned ah[4][4], const unsigned* Wb, int lane){
#pragma unroll
    for(int ks=0;ks<4;ks++){
        const uint4* bb = (const uint4*)(Wb + (ks*32+lane)*36);
#pragma unroll
        for(int jj=0;jj<8;jj++){
            uint4 b = bb[jj];
            mma16(acc[2*jj],  ah[ks][0],ah[ks][1],ah[ks][2],ah[ks][3],b.x,b.y);
            mma16(acc[2*jj+1],ah[ks][0],ah[ks][1],ah[ks][2],ah[ks][3],b.z,b.w);
        }
    }
}

// ---------------------------------------------------------------------------
// pv (fp16): 256 CTAs x 256 thr (R15, passing). 109576 B smem.
// ---------------------------------------------------------------------------
__global__ __launch_bounds__(256,2) void pv_kernel(
    const float* __restrict__ price, const float* __restrict__ liquid,
    const float* __restrict__ bp, const float* __restrict__ bv){
    extern __shared__ float smpv[];
    unsigned* Wres = (unsigned*)smpv;
    float* in_s   = smpv + 18432;
    float* bias_s = smpv + 27136;
    int cb=blockIdx.x, isv=cb>=128, rb=(cb&127)*64;
    const float* in_g = (isv? liquid: price) + (size_t)rb*128;
    const unsigned* packA = isv? g_Wvh : g_Wph;
    const unsigned* packB = isv? g_Wfvh: g_Wfph;
    float* outA = (isv? g_v : g_p)  + (size_t)rb*128;
    float* outB = (isv? g_V1: g_P1) + (size_t)rb*128;
    int t=threadIdx.x, w=t>>5, lane=t&31, gid=lane>>2, t4=lane&3;
    int rowgrp=w&3, pk=w>>2, mbase=rowgrp*16;
    uint32_t sb = s2u(smpv);
    uint32_t mb = sb + 27392*4;

    if(t==0) MBAR_INIT(mb, 1);
    __syncthreads();
    if(t==0){
        MBAR_EXPECT(mb, 4*18432 + 64*512 + 1024);
        bulkcp(sb,          packA,        18432, mb);
        bulkcp(sb+18432,    packA+4608,   18432, mb);
        bulkcp(sb+2*18432,  packB,        18432, mb);
        bulkcp(sb+3*18432,  packB+4608,   18432, mb);
        uint32_t ina = sb + 18432*4;
        for(int r=0;r<64;r++) bulkcp(ina + r*544, in_g + r*128, 512, mb);
        bulkcp(sb + 27136*4,       isv? bv: bp,          512, mb);
        bulkcp(sb + 27136*4 + 512, g_biasF + isv*128,    512, mb);
    }

    float acc[16][4];
#pragma unroll
    for(int j=0;j<16;j++)
#pragma unroll
        for(int e=0;e<4;e++) acc[j][e]=0.f;

    mbwait(mb, 0);
    const float* r0 = in_s + (mbase+gid)*136 + 2*t4;
    const float* r1 = r0 + 8*136;

#pragma unroll
    for(int s=0;s<2;s++){
        unsigned ah[4][4];
        const int kb0 = s*64;
#pragma unroll
        for(int ks=0;ks<4;ks++){
            int ko = kb0 + ks*16;
            float2 a0=*(const float2*)&r0[ko],   c0=*(const float2*)&r1[ko];
            float2 a1=*(const float2*)&r0[ko+8], c1=*(const float2*)&r1[ko+8];
            ah[ks][0]=pk2(a0.x,a0.y);
            ah[ks][1]=pk2(c0.x,c0.y);
            ah[ks][2]=pk2(a1.x,a1.y);
            ah[ks][3]=pk2(c1.x,c1.y);
        }
        mmaW(acc, ah, Wres + pk*9216 + s*4608, lane);
    }

    float* outX = pk? outB: outA;
    float* o0 = outX + (size_t)(mbase+gid)*128;
    float* o1 = o0 + 8*128;
#pragma unroll
    for(int j=0;j<16;j++){
        int c=j*8+2*t4;
        float b0=bias_s[pk*128+c], b1=bias_s[pk*128+c+1];
        *(float2*)&o0[c] = make_float2(acc[j][0]+b0, acc[j][1]+b1);
        *(float2*)&o1[c] = make_float2(acc[j][2]+b0, acc[j][3]+b1);
    }
}

// A-fragment build, TWO row-blocks (mi). Bases include +2*t4.
// s: 0/1 prod k0-63/k64-127, 2/3 absdiff. (proven in R16)
DI void buildA2(unsigned ah[4][2][4], const float* pw, const float* v0, int s){
    const int kb0 = (s&1)*64;
    const float* pwk = pw + kb0;
    const float* vk  = v0 + kb0;
#pragma unroll
    for(int ks=0;ks<4;ks++){
        int ko = ks*16;
        float2 pl = *(const float2*)&pwk[ko];
        float2 ph = *(const float2*)&pwk[ko+8];
#pragma unroll
        for(int mi=0;mi<2;mi++){
            const float* vb = vk + mi*16*136;
            float2 a0=*(const float2*)&vb[ko];
            float2 c0=*(const float2*)&vb[8*136+ko];
            float2 a1=*(const float2*)&vb[ko+8];
            float2 c1=*(const float2*)&vb[8*136+ko+8];
            if(s<2){
                ah[ks][mi][0]=pk2(pl.x*a0.x, pl.y*a0.y);
                ah[ks][mi][1]=pk2(pl.x*c0.x, pl.y*c0.y);
                ah[ks][mi][2]=pk2(ph.x*a1.x, ph.y*a1.y);
                ah[ks][mi][3]=pk2(ph.x*c1.x, ph.y*c1.y);
            }else{
                ah[ks][mi][0]=pk2(fabsf(pl.x-a0.x), fabsf(pl.y-a0.y));
                ah[ks][mi][1]=pk2(fabsf(pl.x-c0.x), fabsf(pl.y-c0.y));
                ah[ks][mi][2]=pk2(fabsf(ph.x-a1.x), fabsf(ph.y-a1.y));
                ah[ks][mi][3]=pk2(fabsf(ph.x-c1.x), fabsf(ph.y-c1.y));
            }
        }
    }
}

// Full-width MMA: 2 row-blocks x 8 col-uint4 (all 128 cols).
DI void mmaWf(float (*acc)[16][4], const unsigned ah[4][2][4],
              const unsigned* Wb, int lane){
#pragma unroll
    for(int ks=0;ks<4;ks++){
        const uint4* bb = (const uint4*)(Wb + (ks*32+lane)*36);
#pragma unroll
        for(int jj=0;jj<8;jj++){
            uint4 b = bb[jj];
            mma16(acc[0][2*jj],  ah[ks][0][0],ah[ks][0][1],ah[ks][0][2],ah[ks][0][3],b.x,b.y);
            mma16(acc[0][2*jj+1],ah[ks][0][0],ah[ks][0][1],ah[ks][0][2],ah[ks][0][3],b.z,b.w);
            mma16(acc[1][2*jj],  ah[ks][1][0],ah[ks][1][1],ah[ks][1][2],ah[ks][1][3],b.x,b.y);
            mma16(acc[1][2*jj+1],ah[ks][1][0],ah[ks][1][1],ah[ks][1][2],ah[ks][1][3],b.z,b.w);
        }
    }
}

// GEMM2 slab, A from h2 registers (layout matches acc fragments).
DI void mmaHf(float (*acc)[16][4], const unsigned h2[2][16][2], int s2,
              const unsigned* Wb, int lane){
#pragma unroll
    for(int ks=0;ks<4;ks++){
        int kg = s2*4+ks;
        const uint4* bb = (const uint4*)(Wb + (ks*32+lane)*36);
#pragma unroll
        for(int jj=0;jj<8;jj++){
            uint4 b = bb[jj];
            mma16(acc[0][2*jj],  h2[0][2*kg][0],h2[0][2*kg][1],h2[0][2*kg+1][0],h2[0][2*kg+1][1],b.x,b.y);
            mma16(acc[0][2*jj+1],h2[0][2*kg][0],h2[0][2*kg][1],h2[0][2*kg+1][0],h2[0][2*kg+1][1],b.z,b.w);
            mma16(acc[1][2*jj],  h2[1][2*kg][0],h2[1][2*kg][1],h2[1][2*kg+1][0],h2[1][2*kg+1][1],b.x,b.y);
            mma16(acc[1][2*jj+1],h2[1][2*kg][0],h2[1][2*kg][1],h2[1][2*kg+1][0],h2[1][2*kg+1][1],b.z,b.w);
        }
    }
}

// ---------------------------------------------------------------------------
// pair_main v6: 2048 CTAs x 128 thr / 4 warps, 32 rows per warp (n = w).
// Halves B-fragment smem reads vs R15; h2 stays in registers (no staging).
// Bulk loads + 4-slot W ring (R15 machinery). acc 128 + h2 64 regs (~215).
// smem identical to R15: 113960 B -> 2 CTAs/SM.
// ---------------------------------------------------------------------------
__global__ __launch_bounds__(128,2) void pair_main_kernel(
    const float* __restrict__ b1v, const float* __restrict__ b2v,
    float* __restrict__ out){
    extern __shared__ float sm[];
    unsigned* Wbuf = (unsigned*)sm;
    float* b1_s = sm + 18432;
    float* b2_s = sm + 18560;
    float* v_s  = sm + 18688;
    float* V1_s = sm + 23040;
    float* p_s  = sm + 27392;
    float* P1_s = sm + 27936;
    const int bt=blockIdx.x>>3, pb=blockIdx.x&7;
    const int t=threadIdx.x, w=t>>5, lane=t&31;
    const int gid=lane>>2, t4=lane&3;
    const int n = w;
    uint32_t Wba = s2u(Wbuf);
    uint32_t m0 = Wba + 28480*4;
    uint32_t m1 = m0+8, m2 = m0+16, m3 = m0+24, mt = m0+32;

    if(t==0){
        MBAR_INIT(m0,1); MBAR_INIT(m1,1); MBAR_INIT(m2,1);
        MBAR_INIT(m3,1); MBAR_INIT(mt,1);
    }
    __syncthreads();
    if(t==0){
        MBAR_EXPECT(m0,18432); bulkcp(Wba,         g_W1h,        18432, m0);
        MBAR_EXPECT(m1,18432); bulkcp(Wba+18432,   g_W1h+4608,   18432, m1);
        MBAR_EXPECT(m2,18432); bulkcp(Wba+2*18432, g_W1h+2*4608, 18432, m2);
        MBAR_EXPECT(m3,18432); bulkcp(Wba+3*18432, g_W1h+3*4608, 18432, m3);
        MBAR_EXPECT(mt, 32*512*2 + 4*512*2 + 1024);
        uint32_t vA = s2u(v_s), vB = s2u(V1_s), pA = s2u(p_s), pB = s2u(P1_s);
        const float* vg  = g_v  + (size_t)bt*4096;
        const float* V1g = g_V1 + (size_t)bt*4096;
        for(int m=0;m<32;m++){
            bulkcp(vA + m*544, vg  + m*128, 512, mt);
            bulkcp(vB + m*544, V1g + m*128, 512, mt);
        }
        const float* pg  = g_p  + (size_t)(bt*32+pb*4)*128;
        const float* P1g = g_P1 + (size_t)(bt*32+pb*4)*128;
        for(int nn=0;nn<4;nn++){
            bulkcp(pA + nn*544, pg  + nn*128, 512, mt);
            bulkcp(pB + nn*544, P1g + nn*128, 512, mt);
        }
        bulkcp(s2u(b1_s), b1v, 512, mt);
        bulkcp(s2u(b2_s), b2v, 512, mt);
    }

    float acc[2][16][4];
#pragma unroll
    for(int mi=0;mi<2;mi++)
#pragma unroll
        for(int j=0;j<16;j++)
#pragma unroll
            for(int e=0;e<4;e++) acc[mi][j][e]=0.f;

    mbwait(mt, 0);
    const float* pw = p_s + n*136 + 2*t4;
    const float* v0 = v_s + gid*136 + 2*t4;

    unsigned ah[4][2][4];
    buildA2(ah, pw, v0, 0);
    mbwait(m0, 0);
    mmaWf(acc, ah, Wbuf, lane);
    buildA2(ah, pw, v0, 1);
    mbwait(m1, 0);
    mmaWf(acc, ah, Wbuf+4608, lane);
    __syncthreads();
    if(t==0){
        MBAR_EXPECT(m0,18432); bulkcp(Wba,       g_W2h,      18432, m0);
        MBAR_EXPECT(m1,18432); bulkcp(Wba+18432, g_W2h+4608, 18432, m1);
    }
    buildA2(ah, pw, v0, 2);
    mbwait(m2, 0);
    mmaWf(acc, ah, Wbuf+2*4608, lane);
    buildA2(ah, pw, v0, 3);
    mbwait(m3, 0);
    mmaWf(acc, ah, Wbuf+3*4608, lane);

    // ------- epilogue 1: silu via 4-way batched rcp -> h2 registers ---------
    unsigned h2[2][16][2];
#pragma unroll
    for(int mi=0;mi<2;mi++){
        const float* V0p = &V1_s[(mi*16+gid)*136];
        const float* V1p = V0p + 8*136;
        const float* P1p = &P1_s[n*136];
#pragma unroll
        for(int j=0;j<16;j++){
            int c0=j*8+2*t4;
            float2 P  = *(const float2*)&P1p[c0];
            float2 Bb = *(const float2*)&b1_s[c0];
            float2 Va = *(const float2*)&V0p[c0];
            float2 Vb = *(const float2*)&V1p[c0];
            float x0=acc[mi][j][0]+P.x+Va.x+Bb.x;
            float x1=acc[mi][j][1]+P.y+Va.y+Bb.y;
            float x2=acc[mi][j][2]+P.x+Vb.x+Bb.x;
            float x3=acc[mi][j][3]+P.y+Vb.y+Bb.y;
            float u0=1.f+__expf(-x0), u1=1.f+__expf(-x1);
            float u2=1.f+__expf(-x2), u3=1.f+__expf(-x3);
            float p01=u0*u1, p23=u2*u3;
            float r = frcp(p01*p23);
            float r01 = r*p23, r23 = r*p01;
            x0 = x0*(r01*u1); x1 = x1*(r01*u0);
            x2 = x2*(r23*u3); x3 = x3*(r23*u2);
            h2[mi][j][0]=pk2(x0,x1);
            h2[mi][j][1]=pk2(x2,x3);
            acc[mi][j][0]=0.f; acc[mi][j][1]=0.f;
            acc[mi][j][2]=0.f; acc[mi][j][3]=0.f;
        }
    }

    // ---- GEMM2: W2 slabs (slots 0,1 phase 1), A from h2 registers ----------
    mbwait(m0, 1);
    mmaHf(acc, h2, 0, Wbuf, lane);
    mbwait(m1, 1);
    mmaHf(acc, h2, 1, Wbuf+4608, lane);

    // ------------- epilogue 2: + b2, direct stores --------------------------
    const size_t ob = (size_t)blockIdx.x*16384;
#pragma unroll
    for(int mi=0;mi<2;mi++){
        float* o0 = out + ob + (size_t)(w*32+mi*16+gid)*128;
        float* o1 = o0 + 1024;
#pragma unroll
        for(int j=0;j<16;j++){
            int c=j*8+2*t4;
            *(float2*)&o0[c] = make_float2(acc[mi][j][0]+b2_s[c], acc[mi][j][1]+b2_s[c+1]);
            *(float2*)&o1[c] = make_float2(acc[mi][j][2]+b2_s[c], acc[mi][j][3]+b2_s[c+1]);
        }
    }
}

extern "C" void kernel_launch(void* const* d_in, const int* in_sizes, int n_in,
                              void* d_out, int out_size){
    const float* price =(const float*)d_in[0];
    const float* liquid=(const float*)d_in[1];
    const float* W_p=(const float*)d_in[2];
    const float* b_p=(const float*)d_in[3];
    const float* W_v=(const float*)d_in[4];
    const float* b_v=(const float*)d_in[5];
    const float* W1 =(const float*)d_in[6];
    const float* b1 =(const float*)d_in[7];
    const float* W2 =(const float*)d_in[8];
    const float* b2 =(const float*)d_in[9];
    float* out=(float*)d_out;
    cudaFuncSetAttribute(pv_kernel, cudaFuncAttributeMaxDynamicSharedMemorySize, 110592);
    cudaFuncSetAttribute(pair_main_kernel, cudaFuncAttributeMaxDynamicSharedMemorySize, 114688);
    prep_kernel<<<16, 256>>>(W_p, b_p, W_v, b_v, W1);
    pack16_kernel<<<14, 128>>>(W1, W2, W_p, W_v);
    pv_kernel<<<256, 256, 109576>>>(price, liquid, b_p, b_v);
    pair_main_kernel<<<2048, 128, 113960>>>(b1, b2, out);
}